// round 15
// baseline (speedup 1.0000x reference)
#include <cuda_runtime.h>
#include <cuda_fp16.h>
#include <cstdint>

#define B_  8
#define S_  512
#define D_  1024
#define V_  32000
#define ND_ 8

// ---- base kernel config (BK=32, R6-proven, CTA 256x128) ----
#define BM 256
#define BN 128
#define BKB 32
#define NCHUNKB (D_ / BKB)       // 32
#define ROWB 80
#define AB_STAGE (BM * ROWB)     // 20480
#define BB_STAGE (BN * ROWB)     // 10240
#define SMEM_BASE_TOTAL (2 * AB_STAGE + 2 * BB_STAGE)    // 61440

// ---- heads kernel config: CTA 128x128, BK=32, fp32-B direct ----
#define HM 128
#define HN 128
#define BKH 32
#define NCHUNKH (D_ / BKH)       // 32
#define HAROW 80                 // fp16 A: 64B data + 16 pad
#define HBROW 528                // fp32 B: 512B data + 16 pad
#define HA_STAGE (HM * HAROW)    // 10240
#define HB_STAGE (BKH * HBROW)   // 16896
#define SMEM_HEADS_TOTAL (2 * HA_STAGE + 2 * HB_STAGE)   // 54272

__device__ __half g_hidden[B_ * S_ * D_];
__device__ __half g_hs_h[B_ * S_ * D_];

// ---------------- helpers ----------------
__device__ __forceinline__ uint32_t smem_u32(const void* p) {
    uint32_t a;
    asm("{ .reg .u64 t; cvta.to.shared.u64 t, %1; cvt.u32.u64 %0, t; }" : "=r"(a) : "l"(p));
    return a;
}
__device__ __forceinline__ uint32_t pack_h2(float x, float y) {
    uint32_t d;
    asm("cvt.rn.f16x2.f32 %0, %2, %1;" : "=r"(d) : "f"(x), "f"(y));
    return d;
}
__device__ __forceinline__ float lds_f32(uint32_t a) {
    float v; asm volatile("ld.shared.f32 %0, [%1];" : "=f"(v) : "r"(a)); return v;
}
__device__ __forceinline__ void cp16(uint32_t d, const void* s) {
    asm volatile("cp.async.cg.shared.global [%0], [%1], 16;" :: "r"(d), "l"(s));
}
__device__ __forceinline__ void ldsm_x4(uint32_t* r, uint32_t addr) {
    asm volatile("ldmatrix.sync.aligned.m8n8.x4.shared.b16 {%0,%1,%2,%3}, [%4];"
                 : "=r"(r[0]), "=r"(r[1]), "=r"(r[2]), "=r"(r[3]) : "r"(addr));
}
__device__ __forceinline__ void mma_f16(float* d, const uint32_t* a, const uint32_t* b) {
    asm volatile(
        "mma.sync.aligned.m16n8k16.row.col.f32.f16.f16.f32 "
        "{%0,%1,%2,%3}, {%4,%5,%6,%7}, {%8,%9}, {%0,%1,%2,%3};"
        : "+f"(d[0]), "+f"(d[1]), "+f"(d[2]), "+f"(d[3])
        : "r"(a[0]), "r"(a[1]), "r"(a[2]), "r"(a[3]), "r"(b[0]), "r"(b[1]));
}
__device__ __forceinline__ int clamp_idx(int id) {
    return (id >= 0 && id < ND_) ? id : ND_;
}

// ===========================================================================
// BASE kernel (unchanged): fp32-B transpose path, CTA 256x128, BK=32.
// ===========================================================================
__global__ __launch_bounds__(256, 1) void gemm_base_kernel(
    const float* __restrict__ Wb, const float* __restrict__ bb)
{
    extern __shared__ char smem[];
    const uint32_t sb = smem_u32(smem);
    const __half* A = g_hs_h;
    const int Nld = D_;
    const int m0 = blockIdx.y * BM, n0 = blockIdx.x * BN;

    const int t    = threadIdx.x;
    const int lane = t & 31;
    const int wid  = t >> 5;
    const int wm   = wid >> 1;
    const int wn   = wid & 1;
    const int bn   = t & 127;
    const int bk0  = (t >> 7) * 16;

    const int aRowOff = (wm * 64 + (lane & 15)) * ROWB + (lane >> 4) * 16;
    const int bRowOff = (wn * 64 + (lane & 7) + ((lane >> 4) ? 8 : 0)) * ROWB
                      + ((lane >> 3) & 1) * 16;

    float acc[4][8][4];
    #pragma unroll
    for (int mt = 0; mt < 4; mt++)
        #pragma unroll
        for (int nt = 0; nt < 8; nt++)
            #pragma unroll
            for (int r = 0; r < 4; r++) acc[mt][nt][r] = 0.0f;

    float vpre[16];
    {
        #pragma unroll
        for (int i = 0; i < 4; i++) {
            const int idx = i * 256 + t;
            const int row = idx >> 2, q = idx & 3;
            cp16(sb + row * ROWB + q * 16, A + (size_t)(m0 + row) * D_ + q * 8);
        }
        asm volatile("cp.async.commit_group;" ::: "memory");

        const float* p = Wb + (size_t)bk0 * Nld + n0 + bn;
        #pragma unroll
        for (int kk = 0; kk < 16; kk++) vpre[kk] = p[(size_t)kk * Nld];

        uint32_t hw[8];
        #pragma unroll
        for (int j = 0; j < 8; j++) hw[j] = pack_h2(vpre[2*j], vpre[2*j+1]);
        const uint32_t dst = sb + 2 * AB_STAGE + bn * ROWB + bk0 * 2;
        asm volatile("st.shared.v4.b32 [%0], {%1,%2,%3,%4};" :: "r"(dst),
            "r"(hw[0]), "r"(hw[1]), "r"(hw[2]), "r"(hw[3]) : "memory");
        asm volatile("st.shared.v4.b32 [%0], {%1,%2,%3,%4};" :: "r"(dst + 16),
            "r"(hw[4]), "r"(hw[5]), "r"(hw[6]), "r"(hw[7]) : "memory");

        asm volatile("cp.async.wait_group 0;" ::: "memory");
        __syncthreads();
    }

    for (int c = 0; c < NCHUNKB; c++) {
        const int buf = c & 1;
        const bool has_next = (c + 1 < NCHUNKB);
        const uint32_t aBase  = sb + (buf ? AB_STAGE : 0);
        const uint32_t bBase  = sb + 2 * AB_STAGE + (buf ? BB_STAGE : 0);
        const uint32_t aBaseN = sb + (buf ? 0 : AB_STAGE);
        const uint32_t bBaseN = sb + 2 * AB_STAGE + (buf ? 0 : BB_STAGE);

        if (has_next) {
            const int k0n = (c + 1) * BKB;
            #pragma unroll
            for (int i = 0; i < 4; i++) {
                const int idx = i * 256 + t;
                const int row = idx >> 2, q = idx & 3;
                cp16(aBaseN + row * ROWB + q * 16,
                     A + (size_t)(m0 + row) * D_ + k0n + q * 8);
            }
            asm volatile("cp.async.commit_group;" ::: "memory");
            const float* p = Wb + (size_t)(k0n + bk0) * Nld + n0 + bn;
            #pragma unroll
            for (int kk = 0; kk < 16; kk++) vpre[kk] = p[(size_t)kk * Nld];
        }

        #pragma unroll
        for (int ks = 0; ks < 2; ks++) {
            uint32_t afr[4][4], bfr[4][4];
            #pragma unroll
            for (int mt = 0; mt < 4; mt++)
                ldsm_x4(afr[mt], aBase + aRowOff + mt * 16 * ROWB + ks * 32);
            #pragma unroll
            for (int p4 = 0; p4 < 4; p4++)
                ldsm_x4(bfr[p4], bBase + bRowOff + p4 * 16 * ROWB + ks * 32);
            #pragma unroll
            for (int mt = 0; mt < 4; mt++)
                #pragma unroll
                for (int p4 = 0; p4 < 4; p4++) {
                    mma_f16(acc[mt][2*p4+0], afr[mt], &bfr[p4][0]);
                    mma_f16(acc[mt][2*p4+1], afr[mt], &bfr[p4][2]);
                }
        }

        if (has_next) {
            uint32_t hw[8];
            #pragma unroll
            for (int j = 0; j < 8; j++) hw[j] = pack_h2(vpre[2*j], vpre[2*j+1]);
            const uint32_t dst = bBaseN + bn * ROWB + bk0 * 2;
            asm volatile("st.shared.v4.b32 [%0], {%1,%2,%3,%4};" :: "r"(dst),
                "r"(hw[0]), "r"(hw[1]), "r"(hw[2]), "r"(hw[3]) : "memory");
            asm volatile("st.shared.v4.b32 [%0], {%1,%2,%3,%4};" :: "r"(dst + 16),
                "r"(hw[4]), "r"(hw[5]), "r"(hw[6]), "r"(hw[7]) : "memory");
            asm volatile("cp.async.wait_group 0;" ::: "memory");
        }
        __syncthreads();
    }

    const int gid = lane >> 2, tig = lane & 3;
    #pragma unroll
    for (int mt = 0; mt < 4; mt++) {
        const int r0 = m0 + wm * 64 + mt * 16 + gid;
        #pragma unroll
        for (int nt = 0; nt < 8; nt++) {
            const int col = n0 + wn * 64 + nt * 8 + tig * 2;
            const float2 bv = *reinterpret_cast<const float2*>(bb + col);
            *reinterpret_cast<uint32_t*>(g_hidden + (size_t)r0 * Nld + col) =
                pack_h2(acc[mt][nt][0] + bv.x, acc[mt][nt][1] + bv.y);
            *reinterpret_cast<uint32_t*>(g_hidden + (size_t)(r0 + 8) * Nld + col) =
                pack_h2(acc[mt][nt][2] + bv.x, acc[mt][nt][3] + bv.y);
        }
    }
}

// ===========================================================================
// HEADS kernel: CTA 128x128, BK=32, 8 warps (2m x 4n).
// B read as FP32 directly from W_heads via cp.async ([k][n], 528B rows);
// fragments built with manual LDS.32 + cvt.rn.f16x2 (no convert prepass).
// ===========================================================================
__global__ __launch_bounds__(256, 1) void gemm_heads_kernel(
    const int* __restrict__ dom, const float* __restrict__ Wh,
    const float* __restrict__ bh, float* __restrict__ out)
{
    extern __shared__ char smem[];
    const uint32_t sb = smem_u32(smem);

    const int b = blockIdx.z;
    const int idx = clamp_idx(dom[b]);

    const __half* A   = g_hidden + (size_t)b * S_ * D_;
    const float*  Bw  = Wh + (size_t)idx * D_ * V_;
    const float* bias = bh + (size_t)idx * V_;
    float* C          = out + (size_t)b * S_ * V_;
    const int Nld = V_;
    const int m0 = blockIdx.x * HM, n0 = blockIdx.y * HN;

    const int t    = threadIdx.x;
    const int lane = t & 31;
    const int wid  = t >> 5;
    const int wm   = wid >> 2;       // 0..1 : 64 rows
    const int wn   = wid & 3;        // 0..3 : 32 cols

    const int aRowOff = (wm * 64 + (lane & 15)) * HAROW + (lane >> 4) * 16;
    // manual B frag coords: n within panel, k-lane base
    const int bN    = wn * 32 + (lane >> 2);   // + p4*16, +8 for hi tile
    const int bKl   = (lane & 3) * 2;          // k pair base within k16 step

    // cp.async mapping
    const int aRow0 = t >> 1;                  // A: 2 cp16/thread
    const int aQ0   = (t & 1) * 2;
    // B: 1024 cp16/stage -> 4/thread: idx = i*256+t, row=idx>>5, seg=idx&31

    float acc[4][4][4];
    #pragma unroll
    for (int mt = 0; mt < 4; mt++)
        #pragma unroll
        for (int nt = 0; nt < 4; nt++)
            #pragma unroll
            for (int r = 0; r < 4; r++) acc[mt][nt][r] = 0.0f;

    // ---- prologue: stage 0 ----
    {
        cp16(sb + aRow0 * HAROW + aQ0 * 16,       A + (size_t)(m0 + aRow0) * D_ + aQ0 * 8);
        cp16(sb + aRow0 * HAROW + (aQ0 + 1) * 16, A + (size_t)(m0 + aRow0) * D_ + (aQ0 + 1) * 8);
        #pragma unroll
        for (int i = 0; i < 4; i++) {
            const int idq = i * 256 + t;
            const int row = idq >> 5, seg = idq & 31;
            cp16(sb + 2 * HA_STAGE + row * HBROW + seg * 16,
                 Bw + (size_t)row * Nld + n0 + seg * 4);
        }
        asm volatile("cp.async.commit_group;" ::: "memory");
        asm volatile("cp.async.wait_group 0;" ::: "memory");
        __syncthreads();
    }

    for (int c = 0; c < NCHUNKH; c++) {
        const int buf = c & 1;
        const bool has_next = (c + 1 < NCHUNKH);
        const uint32_t aBase  = sb + (buf ? HA_STAGE : 0);
        const uint32_t bBase  = sb + 2 * HA_STAGE + (buf ? HB_STAGE : 0);
        const uint32_t aBaseN = sb + (buf ? 0 : HA_STAGE);
        const uint32_t bBaseN = sb + 2 * HA_STAGE + (buf ? 0 : HB_STAGE);

        if (has_next) {
            const int k0n = (c + 1) * BKH;
            cp16(aBaseN + aRow0 * HAROW + aQ0 * 16,       A + (size_t)(m0 + aRow0) * D_ + k0n + aQ0 * 8);
            cp16(aBaseN + aRow0 * HAROW + (aQ0 + 1) * 16, A + (size_t)(m0 + aRow0) * D_ + k0n + (aQ0 + 1) * 8);
            #pragma unroll
            for (int i = 0; i < 4; i++) {
                const int idq = i * 256 + t;
                const int row = idq >> 5, seg = idq & 31;
                cp16(bBaseN + row * HBROW + seg * 16,
                     Bw + (size_t)(k0n + row) * Nld + n0 + seg * 4);
            }
            asm volatile("cp.async.commit_group;" ::: "memory");
        }

        #pragma unroll
        for (int ks = 0; ks < 2; ks++) {
            uint32_t afr[4][4], bfr[2][4];
            #pragma unroll
            for (int mt = 0; mt < 4; mt++)
                ldsm_x4(afr[mt], aBase + aRowOff + mt * 16 * HAROW + ks * 32);

            // manual B fragment build (fp32 LDS -> fp16x2), conflict-free
            const int kb = ks * 16 + bKl;
            #pragma unroll
            for (int p4 = 0; p4 < 2; p4++) {
                const uint32_t nb = bBase + (uint32_t)(bN + p4 * 16) * 4;
                bfr[p4][0] = pack_h2(lds_f32(nb + (kb + 0) * HBROW),
                                     lds_f32(nb + (kb + 1) * HBROW));
                bfr[p4][1] = pack_h2(lds_f32(nb + (kb + 8) * HBROW),
                                     lds_f32(nb + (kb + 9) * HBROW));
                bfr[p4][2] = pack_h2(lds_f32(nb + 32 + (kb + 0) * HBROW),
                                     lds_f32(nb + 32 + (kb + 1) * HBROW));
                bfr[p4][3] = pack_h2(lds_f32(nb + 32 + (kb + 8) * HBROW),
                                     lds_f32(nb + 32 + (kb + 9) * HBROW));
            }
            #pragma unroll
            for (int mt = 0; mt < 4; mt++)
                #pragma unroll
                for (int p4 = 0; p4 < 2; p4++) {
                    mma_f16(acc[mt][2*p4+0], afr[mt], &bfr[p4][0]);
                    mma_f16(acc[mt][2*p4+1], afr[mt], &bfr[p4][2]);
                }
        }

        if (has_next) {
            asm volatile("cp.async.wait_group 0;" ::: "memory");
        }
        __syncthreads();
    }

    const int gid = lane >> 2, tig = lane & 3;
    #pragma unroll
    for (int mt = 0; mt < 4; mt++) {
        const int r0 = m0 + wm * 64 + mt * 16 + gid;
        #pragma unroll
        for (int nt = 0; nt < 4; nt++) {
            const int col = n0 + wn * 32 + nt * 8 + tig * 2;
            const float2 bv = *reinterpret_cast<const float2*>(bias + col);
            *reinterpret_cast<float2*>(C + (size_t)r0 * Nld + col) =
                make_float2(acc[mt][nt][0] + bv.x, acc[mt][nt][1] + bv.y);
            *reinterpret_cast<float2*>(C + (size_t)(r0 + 8) * Nld + col) =
                make_float2(acc[mt][nt][2] + bv.x, acc[mt][nt][3] + bv.y);
        }
    }
}

// ---------------- aux kernel ----------------
__global__ __launch_bounds__(256) void round_hs_kernel(const float* __restrict__ hs) {
    const int i = (blockIdx.x * 256 + threadIdx.x) * 4;
    float4 v = *reinterpret_cast<const float4*>(hs + i);
    uint2 o;
    o.x = pack_h2(v.x, v.y);
    o.y = pack_h2(v.z, v.w);
    *reinterpret_cast<uint2*>(g_hs_h + i) = o;
}

// ---------------- launch ----------------
extern "C" void kernel_launch(void* const* d_in, const int* in_sizes, int n_in,
                              void* d_out, int out_size)
{
    const float* hs      = (const float*)d_in[0];
    const int*   dom     = (const int*)  d_in[1];
    const float* W_base  = (const float*)d_in[2];
    const float* b_base  = (const float*)d_in[3];
    const float* W_heads = (const float*)d_in[4];
    const float* b_heads = (const float*)d_in[5];
    float* out = (float*)d_out;

    static bool attr_set = false;
    if (!attr_set) {
        cudaFuncSetAttribute(gemm_base_kernel,  cudaFuncAttributeMaxDynamicSharedMemorySize, SMEM_BASE_TOTAL);
        cudaFuncSetAttribute(gemm_heads_kernel, cudaFuncAttributeMaxDynamicSharedMemorySize, SMEM_HEADS_TOTAL);
        attr_set = true;
    }

    round_hs_kernel<<<(B_ * S_ * D_) / (256 * 4), 256>>>(hs);

    dim3 gA(D_ / BN, (B_ * S_) / BM, 1);          // (8, 16, 1)
    gemm_base_kernel<<<gA, 256, SMEM_BASE_TOTAL>>>(W_base, b_base);

    dim3 gB(S_ / HM, V_ / HN, B_);                // (4, 250, 8) m fastest
    gemm_heads_kernel<<<gB, 256, SMEM_HEADS_TOTAL>>>(dom, W_heads, b_heads, out);
}

// round 16
// speedup vs baseline: 1.7347x; 1.7347x over previous
#include <cuda_runtime.h>
#include <cuda_fp16.h>
#include <cstdint>

#define B_  8
#define S_  512
#define D_  1024
#define V_  32000
#define ND_ 8

#define BM 256
#define BN 128

// ---- base kernel config (BK=32) ----
#define BKB 32
#define NCHUNKB (D_ / BKB)       // 32
#define ROWB 80
#define AB_STAGE (BM * ROWB)     // 20480
#define BB_STAGE (BN * ROWB)     // 10240
#define SMEM_BASE_TOTAL (2 * AB_STAGE + 2 * BB_STAGE)    // 61440

// ---- heads kernel config (BK=64) ----
#define BKH 64
#define NCHUNKH (D_ / BKH)       // 16
#define HAROW 144                // 128B data + 16 pad
#define HBROW 272                // 256B data + 16 pad
#define HA_STAGE (BM * HAROW)    // 36864
#define HB_STAGE (BKH * HBROW)   // 17408
#define SMEM_HEADS_TOTAL (2 * HA_STAGE + 2 * HB_STAGE)   // 108544

__device__ __half g_hidden[B_ * S_ * D_];
__device__ __half g_hs_h[B_ * S_ * D_];
__device__ __half g_whB[(size_t)B_ * D_ * V_];

// ---------------- helpers ----------------
__device__ __forceinline__ uint32_t smem_u32(const void* p) {
    uint32_t a;
    asm("{ .reg .u64 t; cvta.to.shared.u64 t, %1; cvt.u32.u64 %0, t; }" : "=r"(a) : "l"(p));
    return a;
}
__device__ __forceinline__ uint32_t pack_h2(float x, float y) {
    uint32_t d;
    asm("cvt.rn.f16x2.f32 %0, %2, %1;" : "=r"(d) : "f"(x), "f"(y));
    return d;
}
__device__ __forceinline__ void cp16(uint32_t d, const void* s) {
    asm volatile("cp.async.cg.shared.global [%0], [%1], 16;" :: "r"(d), "l"(s));
}
__device__ __forceinline__ void ldsm_x4(uint32_t* r, uint32_t addr) {
    asm volatile("ldmatrix.sync.aligned.m8n8.x4.shared.b16 {%0,%1,%2,%3}, [%4];"
                 : "=r"(r[0]), "=r"(r[1]), "=r"(r[2]), "=r"(r[3]) : "r"(addr));
}
__device__ __forceinline__ void ldsm_x4_t(uint32_t* r, uint32_t addr) {
    asm volatile("ldmatrix.sync.aligned.m8n8.x4.trans.shared.b16 {%0,%1,%2,%3}, [%4];"
                 : "=r"(r[0]), "=r"(r[1]), "=r"(r[2]), "=r"(r[3]) : "r"(addr));
}
__device__ __forceinline__ void mma_f16(float* d, const uint32_t* a, const uint32_t* b) {
    asm volatile(
        "mma.sync.aligned.m16n8k16.row.col.f32.f16.f16.f32 "
        "{%0,%1,%2,%3}, {%4,%5,%6,%7}, {%8,%9}, {%0,%1,%2,%3};"
        : "+f"(d[0]), "+f"(d[1]), "+f"(d[2]), "+f"(d[3])
        : "r"(a[0]), "r"(a[1]), "r"(a[2]), "r"(a[3]), "r"(b[0]), "r"(b[1]));
}
__device__ __forceinline__ int clamp_idx(int id) {
    return (id >= 0 && id < ND_) ? id : ND_;
}

// ===========================================================================
// BASE kernel: fp32-B transpose path, CTA 256x128, BK=32.
// ===========================================================================
__global__ __launch_bounds__(256, 1) void gemm_base_kernel(
    const float* __restrict__ Wb, const float* __restrict__ bb)
{
    extern __shared__ char smem[];
    const uint32_t sb = smem_u32(smem);
    const __half* A = g_hs_h;
    const int Nld = D_;
    const int m0 = blockIdx.y * BM, n0 = blockIdx.x * BN;

    const int t    = threadIdx.x;
    const int lane = t & 31;
    const int wid  = t >> 5;
    const int wm   = wid >> 1;
    const int wn   = wid & 1;
    const int bn   = t & 127;
    const int bk0  = (t >> 7) * 16;

    const int aRowOff = (wm * 64 + (lane & 15)) * ROWB + (lane >> 4) * 16;
    const int bRowOff = (wn * 64 + (lane & 7) + ((lane >> 4) ? 8 : 0)) * ROWB
                      + ((lane >> 3) & 1) * 16;

    float acc[4][8][4];
    #pragma unroll
    for (int mt = 0; mt < 4; mt++)
        #pragma unroll
        for (int nt = 0; nt < 8; nt++)
            #pragma unroll
            for (int r = 0; r < 4; r++) acc[mt][nt][r] = 0.0f;

    float vpre[16];
    {
        #pragma unroll
        for (int i = 0; i < 4; i++) {
            const int idx = i * 256 + t;
            const int row = idx >> 2, q = idx & 3;
            cp16(sb + row * ROWB + q * 16, A + (size_t)(m0 + row) * D_ + q * 8);
        }
        asm volatile("cp.async.commit_group;" ::: "memory");

        const float* p = Wb + (size_t)bk0 * Nld + n0 + bn;
        #pragma unroll
        for (int kk = 0; kk < 16; kk++) vpre[kk] = p[(size_t)kk * Nld];

        uint32_t hw[8];
        #pragma unroll
        for (int j = 0; j < 8; j++) hw[j] = pack_h2(vpre[2*j], vpre[2*j+1]);
        const uint32_t dst = sb + 2 * AB_STAGE + bn * ROWB + bk0 * 2;
        asm volatile("st.shared.v4.b32 [%0], {%1,%2,%3,%4};" :: "r"(dst),
            "r"(hw[0]), "r"(hw[1]), "r"(hw[2]), "r"(hw[3]) : "memory");
        asm volatile("st.shared.v4.b32 [%0], {%1,%2,%3,%4};" :: "r"(dst + 16),
            "r"(hw[4]), "r"(hw[5]), "r"(hw[6]), "r"(hw[7]) : "memory");

        asm volatile("cp.async.wait_group 0;" ::: "memory");
        __syncthreads();
    }

    for (int c = 0; c < NCHUNKB; c++) {
        const int buf = c & 1;
        const bool has_next = (c + 1 < NCHUNKB);
        const uint32_t aBase  = sb + (buf ? AB_STAGE : 0);
        const uint32_t bBase  = sb + 2 * AB_STAGE + (buf ? BB_STAGE : 0);
        const uint32_t aBaseN = sb + (buf ? 0 : AB_STAGE);
        const uint32_t bBaseN = sb + 2 * AB_STAGE + (buf ? 0 : BB_STAGE);

        if (has_next) {
            const int k0n = (c + 1) * BKB;
            #pragma unroll
            for (int i = 0; i < 4; i++) {
                const int idx = i * 256 + t;
                const int row = idx >> 2, q = idx & 3;
                cp16(aBaseN + row * ROWB + q * 16,
                     A + (size_t)(m0 + row) * D_ + k0n + q * 8);
            }
            asm volatile("cp.async.commit_group;" ::: "memory");
            const float* p = Wb + (size_t)(k0n + bk0) * Nld + n0 + bn;
            #pragma unroll
            for (int kk = 0; kk < 16; kk++) vpre[kk] = p[(size_t)kk * Nld];
        }

        #pragma unroll
        for (int ks = 0; ks < 2; ks++) {
            uint32_t afr[4][4], bfr[4][4];
            #pragma unroll
            for (int mt = 0; mt < 4; mt++)
                ldsm_x4(afr[mt], aBase + aRowOff + mt * 16 * ROWB + ks * 32);
            #pragma unroll
            for (int p4 = 0; p4 < 4; p4++)
                ldsm_x4(bfr[p4], bBase + bRowOff + p4 * 16 * ROWB + ks * 32);
            #pragma unroll
            for (int mt = 0; mt < 4; mt++)
                #pragma unroll
                for (int p4 = 0; p4 < 4; p4++) {
                    mma_f16(acc[mt][2*p4+0], afr[mt], &bfr[p4][0]);
                    mma_f16(acc[mt][2*p4+1], afr[mt], &bfr[p4][2]);
                }
        }

        if (has_next) {
            uint32_t hw[8];
            #pragma unroll
            for (int j = 0; j < 8; j++) hw[j] = pack_h2(vpre[2*j], vpre[2*j+1]);
            const uint32_t dst = bBaseN + bn * ROWB + bk0 * 2;
            asm volatile("st.shared.v4.b32 [%0], {%1,%2,%3,%4};" :: "r"(dst),
                "r"(hw[0]), "r"(hw[1]), "r"(hw[2]), "r"(hw[3]) : "memory");
            asm volatile("st.shared.v4.b32 [%0], {%1,%2,%3,%4};" :: "r"(dst + 16),
                "r"(hw[4]), "r"(hw[5]), "r"(hw[6]), "r"(hw[7]) : "memory");
            asm volatile("cp.async.wait_group 0;" ::: "memory");
        }
        __syncthreads();
    }

    const int gid = lane >> 2, tig = lane & 3;
    #pragma unroll
    for (int mt = 0; mt < 4; mt++) {
        const int r0 = m0 + wm * 64 + mt * 16 + gid;
        #pragma unroll
        for (int nt = 0; nt < 8; nt++) {
            const int col = n0 + wn * 64 + nt * 8 + tig * 2;
            const float2 bv = *reinterpret_cast<const float2*>(bb + col);
            *reinterpret_cast<uint32_t*>(g_hidden + (size_t)r0 * Nld + col) =
                pack_h2(acc[mt][nt][0] + bv.x, acc[mt][nt][1] + bv.y);
            *reinterpret_cast<uint32_t*>(g_hidden + (size_t)(r0 + 8) * Nld + col) =
                pack_h2(acc[mt][nt][2] + bv.x, acc[mt][nt][3] + bv.y);
        }
    }
}

// ===========================================================================
// HEADS kernel (R10-proven): BK=64, fp16 B via cp.async + ldmatrix.trans.
// grid = (m:2, n:250, b:8), m fastest for L2 sharing of B.
// ===========================================================================
__global__ __launch_bounds__(256, 1) void gemm_heads_kernel(
    const int* __restrict__ dom, const float* __restrict__ bh,
    float* __restrict__ out)
{
    extern __shared__ char smem[];
    const uint32_t sb = smem_u32(smem);

    const int b = blockIdx.z;
    const int idx = clamp_idx(dom[b]);
    int ob = b;
    for (int bb = 0; bb < b; bb++)
        if (clamp_idx(dom[bb]) == idx) { ob = bb; break; }

    const __half* A   = g_hidden + (size_t)b * S_ * D_;
    const __half* Bh  = g_whB + (size_t)ob * D_ * V_;
    const float* bias = bh + (size_t)idx * V_;
    float* C          = out + (size_t)b * S_ * V_;
    const int Nld = V_;
    const int m0 = blockIdx.x * BM, n0 = blockIdx.y * BN;

    const int t    = threadIdx.x;
    const int lane = t & 31;
    const int wid  = t >> 5;
    const int wm   = wid >> 1;
    const int wn   = wid & 1;

    const int aRowOff  = (wm * 64 + (lane & 15)) * HAROW + (lane >> 4) * 16;
    const int bLaneOff = ((lane & 7) + ((lane >> 3) & 1) * 8) * HBROW + (lane >> 4) * 16;

    float acc[4][8][4];
    #pragma unroll
    for (int mt = 0; mt < 4; mt++)
        #pragma unroll
        for (int nt = 0; nt < 8; nt++)
            #pragma unroll
            for (int r = 0; r < 4; r++) acc[mt][nt][r] = 0.0f;

    // prologue: stage chunk 0.  A: 256 rows x 8 segs = 2048 -> 8/thread.
    //                           B: 64 rows x 16 segs = 1024 -> 4/thread.
    {
        #pragma unroll
        for (int i = 0; i < 8; i++) {
            const int idq = i * 256 + t;
            const int row = idq >> 3, q = idq & 7;
            cp16(sb + row * HAROW + q * 16, A + (size_t)(m0 + row) * D_ + q * 8);
        }
        #pragma unroll
        for (int i = 0; i < 4; i++) {
            const int idq = i * 256 + t;
            const int row = idq >> 4, seg = idq & 15;
            cp16(sb + 2 * HA_STAGE + row * HBROW + seg * 16,
                 Bh + (size_t)row * Nld + n0 + seg * 8);
        }
        asm volatile("cp.async.commit_group;" ::: "memory");
        asm volatile("cp.async.wait_group 0;" ::: "memory");
        __syncthreads();
    }

    for (int c = 0; c < NCHUNKH; c++) {
        const int buf = c & 1;
        const bool has_next = (c + 1 < NCHUNKH);
        const uint32_t aBase  = sb + (buf ? HA_STAGE : 0);
        const uint32_t bBase  = sb + 2 * HA_STAGE + (buf ? HB_STAGE : 0);
        const uint32_t aBaseN = sb + (buf ? 0 : HA_STAGE);
        const uint32_t bBaseN = sb + 2 * HA_STAGE + (buf ? 0 : HB_STAGE);

        if (has_next) {
            const int k0n = (c + 1) * BKH;
            #pragma unroll
            for (int i = 0; i < 8; i++) {
                const int idq = i * 256 + t;
                const int row = idq >> 3, q = idq & 7;
                cp16(aBaseN + row * HAROW + q * 16,
                     A + (size_t)(m0 + row) * D_ + k0n + q * 8);
            }
            #pragma unroll
            for (int i = 0; i < 4; i++) {
                const int idq = i * 256 + t;
                const int row = idq >> 4, seg = idq & 15;
                cp16(bBaseN + row * HBROW + seg * 16,
                     Bh + (size_t)(k0n + row) * Nld + n0 + seg * 8);
            }
            asm volatile("cp.async.commit_group;" ::: "memory");
        }

        #pragma unroll
        for (int ks = 0; ks < 4; ks++) {
            uint32_t afr[4][4], bfr[4][4];
            #pragma unroll
            for (int mt = 0; mt < 4; mt++)
                ldsm_x4(afr[mt], aBase + aRowOff + mt * 16 * HAROW + ks * 32);
            #pragma unroll
            for (int p4 = 0; p4 < 4; p4++)
                ldsm_x4_t(bfr[p4], bBase + bLaneOff + ks * 16 * HBROW
                                 + (wn * 64 + p4 * 16) * 2);
            #pragma unroll
            for (int mt = 0; mt < 4; mt++)
                #pragma unroll
                for (int p4 = 0; p4 < 4; p4++) {
                    mma_f16(acc[mt][2*p4+0], afr[mt], &bfr[p4][0]);
                    mma_f16(acc[mt][2*p4+1], afr[mt], &bfr[p4][2]);
                }
        }

        if (has_next) {
            asm volatile("cp.async.wait_group 0;" ::: "memory");
        }
        __syncthreads();
    }

    const int gid = lane >> 2, tig = lane & 3;
    #pragma unroll
    for (int mt = 0; mt < 4; mt++) {
        const int r0 = m0 + wm * 64 + mt * 16 + gid;
        #pragma unroll
        for (int nt = 0; nt < 8; nt++) {
            const int col = n0 + wn * 64 + nt * 8 + tig * 2;
            const float2 bv = *reinterpret_cast<const float2*>(bias + col);
            *reinterpret_cast<float2*>(C + (size_t)r0 * Nld + col) =
                make_float2(acc[mt][nt][0] + bv.x, acc[mt][nt][1] + bv.y);
            *reinterpret_cast<float2*>(C + (size_t)(r0 + 8) * Nld + col) =
                make_float2(acc[mt][nt][2] + bv.x, acc[mt][nt][3] + bv.y);
        }
    }
}

// ---------------- aux kernels ----------------
__global__ __launch_bounds__(256) void round_hs_kernel(const float* __restrict__ hs) {
    const int i = (blockIdx.x * 256 + threadIdx.x) * 4;
    float4 v = *reinterpret_cast<const float4*>(hs + i);
    uint2 o;
    o.x = pack_h2(v.x, v.y);
    o.y = pack_h2(v.z, v.w);
    *reinterpret_cast<uint2*>(g_hs_h + i) = o;
}

__global__ __launch_bounds__(256) void convert_w_kernel(
    const int* __restrict__ dom, const float* __restrict__ Wh)
{
    const int b = blockIdx.y;
    const int idx = clamp_idx(dom[b]);
    for (int bb = 0; bb < b; bb++)
        if (clamp_idx(dom[bb]) == idx) return;

    const size_t i = ((size_t)blockIdx.x * 256 + threadIdx.x) * 8;
    const float* src = Wh + (size_t)idx * D_ * V_ + i;
    __half* dst = g_whB + (size_t)b * D_ * V_ + i;
    float4 v0 = *reinterpret_cast<const float4*>(src);
    float4 v1 = *reinterpret_cast<const float4*>(src + 4);
    uint4 o;
    o.x = pack_h2(v0.x, v0.y);
    o.y = pack_h2(v0.z, v0.w);
    o.z = pack_h2(v1.x, v1.y);
    o.w = pack_h2(v1.z, v1.w);
    *reinterpret_cast<uint4*>(dst) = o;
}

// ---------------- launch ----------------
extern "C" void kernel_launch(void* const* d_in, const int* in_sizes, int n_in,
                              void* d_out, int out_size)
{
    const float* hs      = (const float*)d_in[0];
    const int*   dom     = (const int*)  d_in[1];
    const float* W_base  = (const float*)d_in[2];
    const float* b_base  = (const float*)d_in[3];
    const float* W_heads = (const float*)d_in[4];
    const float* b_heads = (const float*)d_in[5];
    float* out = (float*)d_out;

    static cudaStream_t s2 = nullptr;
    static cudaEvent_t evFork = nullptr, evJoin = nullptr;
    if (s2 == nullptr) {
        cudaStreamCreateWithFlags(&s2, cudaStreamNonBlocking);
        cudaEventCreateWithFlags(&evFork, cudaEventDisableTiming);
        cudaEventCreateWithFlags(&evJoin, cudaEventDisableTiming);
        cudaFuncSetAttribute(gemm_base_kernel,  cudaFuncAttributeMaxDynamicSharedMemorySize, SMEM_BASE_TOTAL);
        cudaFuncSetAttribute(gemm_heads_kernel, cudaFuncAttributeMaxDynamicSharedMemorySize, SMEM_HEADS_TOTAL);
    }

    // Fork: convert_w on side stream, round+base on main stream (independent).
    cudaEventRecord(evFork, 0);
    cudaStreamWaitEvent(s2, evFork, 0);

    dim3 gC((D_ * V_) / (256 * 8), B_);           // (16000, 8)
    convert_w_kernel<<<gC, 256, 0, s2>>>(dom, W_heads);
    cudaEventRecord(evJoin, s2);

    round_hs_kernel<<<(B_ * S_ * D_) / (256 * 4), 256>>>(hs);

    dim3 gA(D_ / BN, (B_ * S_) / BM, 1);          // (8, 16, 1)
    gemm_base_kernel<<<gA, 256, SMEM_BASE_TOTAL>>>(W_base, b_base);

    // Join: heads needs both g_hidden (main) and g_whB (s2).
    cudaStreamWaitEvent(0, evJoin, 0);

    dim3 gB(S_ / BM, V_ / BN, B_);                // (2, 250, 8) m fastest
    gemm_heads_kernel<<<gB, 256, SMEM_HEADS_TOTAL>>>(dom, b_heads, out);
}